// round 1
// baseline (speedup 1.0000x reference)
#include <cuda_runtime.h>

#define TT 8192
#define CC 64
#define BDIM 512
#define LOG2T 13

__device__ __forceinline__ float2 cmulf(float2 a, float2 b) {
    return make_float2(fmaf(a.x, b.x, -a.y * b.y), fmaf(a.x, b.y, a.y * b.x));
}

__global__ void __launch_bounds__(BDIM, 2)
surrogate_kernel(const float* __restrict__ wave,
                 const float* __restrict__ phases,
                 const float* __restrict__ mask,
                 float* __restrict__ out)
{
    extern __shared__ float2 buf[];   // 8192 float2 = 64 KB
    const int tid = threadIdx.x;
    const int blk = blockIdx.x;
    const int b  = blk >> 5;          // 32 channel-pairs per batch
    const int c0 = (blk & 31) * 2;

    const float m0 = mask[b * CC + c0];
    const float m1 = mask[b * CC + c0 + 1];
    const bool sel0 = m0 < 0.5f;
    const bool sel1 = m1 < 0.5f;

    const float* wbase = wave + ((size_t)b * TT) * CC + c0;
    float*       obase = out  + ((size_t)b * TT) * CC + c0;

    // Neither channel selected: pure copy, skip all FFT work.
    if (!sel0 && !sel1) {
        for (int t = tid; t < TT; t += BDIM)
            *(float2*)(obase + (size_t)t * CC) = *(const float2*)(wbase + (size_t)t * CC);
        return;
    }

    // Load 2 channels packed as complex: re = ch c0, im = ch c0+1.
    for (int t = tid; t < TT; t += BDIM)
        buf[t] = *(const float2*)(wbase + (size_t)t * CC);
    __syncthreads();

    const float PI_F   = 3.14159265358979f;
    const float TWO_PI = 6.28318530717959f;

    // ---------------- Forward FFT: fused radix-2x2 DIF passes ----------------
    // Stages (4096,2048),(1024,512),(256,128),(64,32),(16,8),(4,2), then m=1.
    // Natural input -> bit-reversed output order.
    #pragma unroll
    for (int m = 4096; m >= 4; m >>= 2) {
        const int h = m >> 1;
        const float asc = -PI_F / (float)m;
        #pragma unroll
        for (int it = 0; it < (TT / 4) / BDIM; ++it) {
            int q  = tid + it * BDIM;
            int jm = q & (h - 1);
            int d  = 4 * (q - jm) + jm;
            float2 x0 = buf[d], x1 = buf[d + h], x2 = buf[d + 2 * h], x3 = buf[d + 3 * h];
            float s, c; __sincosf(asc * (float)jm, &s, &c);
            float2 u = make_float2(c, s);                        // e^{-i pi jm/m}
            float2 v = make_float2(c * c - s * s, 2.f * c * s);  // u^2
            float2 A  = make_float2(x0.x + x2.x, x0.y + x2.y);
            float2 Bq = cmulf(u, make_float2(x0.x - x2.x, x0.y - x2.y));
            float2 Cq = make_float2(x1.x + x3.x, x1.y + x3.y);
            float2 tD = cmulf(u, make_float2(x1.x - x3.x, x1.y - x3.y));
            float2 D  = make_float2(tD.y, -tD.x);                // * (-i)
            buf[d]         = make_float2(A.x + Cq.x, A.y + Cq.y);
            buf[d + h]     = cmulf(v, make_float2(A.x - Cq.x, A.y - Cq.y));
            buf[d + 2 * h] = make_float2(Bq.x + D.x, Bq.y + D.y);
            buf[d + 3 * h] = cmulf(v, make_float2(Bq.x - D.x, Bq.y - D.y));
        }
        __syncthreads();
    }
    // Final DIF stage m=1 (twiddle = 1).
    for (int i = tid; i < TT / 2; i += BDIM) {
        float2 a = buf[2 * i], bb = buf[2 * i + 1];
        buf[2 * i]     = make_float2(a.x + bb.x, a.y + bb.y);
        buf[2 * i + 1] = make_float2(a.x - bb.x, a.y - bb.y);
    }
    __syncthreads();

    // ---------------- Spectral stage (in bit-reversed domain) ----------------
    // Z = FFT(x0 + i x1). Unpack: F0[k]=(Z[k]+conj(Z[-k]))/2, F1[k]=(Z[k]-conj(Z[-k]))/(2i).
    // A0,A1 amplitudes (symmetric in k). Y_c[k] = A_c e^{i phi_c[k]}.
    // S_c[k] = Hermitian part of Y_c (so ifft(S_c) = Re(ifft(Y_c))), W = S0 + i S1.
    // S_c[T-k] = conj(S_c[k]) -> each pair {k, T-k} computed by one thread.
    {
        const float* pbase = phases + ((size_t)b * TT) * CC + c0;
        for (int pos = tid; pos < TT; pos += BDIM) {
            int k = __brev(pos) >> (32 - LOG2T);
            if (k > TT / 2) continue;                 // partner thread's k would be > T/2
            int kn = (TT - k) & (TT - 1);
            int pn = __brev(kn) >> (32 - LOG2T);
            float2 Zk = buf[pos];
            float2 Zn = buf[pn];
            float re0 = 0.5f * (Zk.x + Zn.x), im0 = 0.5f * (Zk.y - Zn.y);
            float re1 = 0.5f * (Zk.y + Zn.y), im1 = 0.5f * (Zn.x - Zk.x);
            float A0 = sqrtf(fmaf(re0, re0, im0 * im0));
            float A1 = sqrtf(fmaf(re1, re1, im1 * im1));
            float2 phk = *(const float2*)(pbase + (size_t)k  * CC);
            float2 phn = *(const float2*)(pbase + (size_t)kn * CC);
            // phi = u*2pi; shift by -pi into __sincosf's accurate range, negate results.
            float s0k, c0k, s0n, c0n, s1k, c1k, s1n, c1n;
            __sincosf(fmaf(phk.x, TWO_PI, -PI_F), &s0k, &c0k); s0k = -s0k; c0k = -c0k;
            __sincosf(fmaf(phn.x, TWO_PI, -PI_F), &s0n, &c0n); s0n = -s0n; c0n = -c0n;
            __sincosf(fmaf(phk.y, TWO_PI, -PI_F), &s1k, &c1k); s1k = -s1k; c1k = -c1k;
            __sincosf(fmaf(phn.y, TWO_PI, -PI_F), &s1n, &c1n); s1n = -s1n; c1n = -c1n;
            float S0x = 0.5f * A0 * (c0k + c0n), S0y = 0.5f * A0 * (s0k - s0n);
            float S1x = 0.5f * A1 * (c1k + c1n), S1y = 0.5f * A1 * (s1k - s1n);
            buf[pos] = make_float2(S0x - S1y, S0y + S1x);          // W[k]
            buf[pn]  = make_float2(S0x + S1y, S1x - S0y);          // W[T-k] = conj(S0)+i conj(S1)
        }
    }
    __syncthreads();

    // ---------------- Inverse FFT: fused radix-2x2 DIT passes ----------------
    // Stages (1,2),(4,8),(16,32),(64,128),(256,512),(1024,2048), then m=4096.
    // Bit-reversed input -> natural output order.
    #pragma unroll
    for (int m = 1; m <= 1024; m <<= 2) {
        const float asc = PI_F / (float)(2 * m);
        #pragma unroll
        for (int it = 0; it < (TT / 4) / BDIM; ++it) {
            int q  = tid + it * BDIM;
            int jm = q & (m - 1);
            int d  = 4 * (q - jm) + jm;
            float2 x0 = buf[d], x1 = buf[d + m], x2 = buf[d + 2 * m], x3 = buf[d + 3 * m];
            float s, c; __sincosf(asc * (float)jm, &s, &c);
            float2 w2 = make_float2(c, s);                         // e^{+i pi jm/(2m)}
            float2 w1 = make_float2(c * c - s * s, 2.f * c * s);   // w2^2 = e^{+i pi jm/m}
            float2 t1 = cmulf(w1, x1);
            float2 A  = make_float2(x0.x + t1.x, x0.y + t1.y);
            float2 Bq = make_float2(x0.x - t1.x, x0.y - t1.y);
            float2 t3 = cmulf(w1, x3);
            float2 Cq = make_float2(x2.x + t3.x, x2.y + t3.y);
            float2 D  = make_float2(x2.x - t3.x, x2.y - t3.y);
            float2 uu = cmulf(w2, Cq);
            float2 vv = cmulf(w2, D);
            float2 iv = make_float2(-vv.y, vv.x);                  // * (+i)
            buf[d]         = make_float2(A.x + uu.x, A.y + uu.y);
            buf[d + 2 * m] = make_float2(A.x - uu.x, A.y - uu.y);
            buf[d + m]     = make_float2(Bq.x + iv.x, Bq.y + iv.y);
            buf[d + 3 * m] = make_float2(Bq.x - iv.x, Bq.y - iv.y);
        }
        __syncthreads();
    }
    // Final DIT stage m=4096.
    {
        const float asc = PI_F / 4096.0f;
        for (int i = tid; i < TT / 2; i += BDIM) {
            float2 a = buf[i], bb = buf[i + TT / 2];
            float s, c; __sincosf(asc * (float)i, &s, &c);
            float2 wb = cmulf(make_float2(c, s), bb);
            buf[i]          = make_float2(a.x + wb.x, a.y + wb.y);
            buf[i + TT / 2] = make_float2(a.x - wb.x, a.y - wb.y);
        }
    }
    __syncthreads();

    // ---------------- Output: scale by 1/T, per-channel Bernoulli select ----------------
    const float inv = 1.0f / (float)TT;
    for (int t = tid; t < TT; t += BDIM) {
        float2 sres = buf[t];
        float ox, oy;
        if (sel0) ox = sres.x * inv; else ox = wbase[(size_t)t * CC];
        if (sel1) oy = sres.y * inv; else oy = wbase[(size_t)t * CC + 1];
        *(float2*)(obase + (size_t)t * CC) = make_float2(ox, oy);
    }
}

extern "C" void kernel_launch(void* const* d_in, const int* in_sizes, int n_in,
                              void* d_out, int out_size)
{
    const float* wave   = (const float*)d_in[0];
    const float* phases = (const float*)d_in[1];
    const float* mask   = (const float*)d_in[2];
    float* out = (float*)d_out;

    cudaFuncSetAttribute(surrogate_kernel,
                         cudaFuncAttributeMaxDynamicSharedMemorySize, TT * sizeof(float2));
    // 64 batches * 32 channel-pairs = 2048 CTAs
    surrogate_kernel<<<2048, BDIM, TT * sizeof(float2)>>>(wave, phases, mask, out);
}

// round 3
// speedup vs baseline: 1.3443x; 1.3443x over previous
#include <cuda_runtime.h>

#define TT 8192
#define CC 64
#define BDIM 512
#define LOG2T 13
// Conflict-free padding: +2 float2 per 16. bank(i) = 2*(i%16) + 4*((i/16)%8) mod 32.
#define PIDX(i) ((i) + (((i) >> 4) << 1))
#define SMEMN (TT + ((TT >> 4) << 1))   // 9216 float2 = 72 KB

__device__ __forceinline__ float2 cadd(float2 a, float2 b){ return make_float2(a.x+b.x, a.y+b.y); }
__device__ __forceinline__ float2 csub(float2 a, float2 b){ return make_float2(a.x-b.x, a.y-b.y); }
__device__ __forceinline__ float2 cmulf(float2 a, float2 b){
    return make_float2(fmaf(a.x, b.x, -a.y*b.y), fmaf(a.x, b.y, a.y*b.x));
}
__device__ __forceinline__ float2 cmuli (float2 a){ return make_float2(-a.y,  a.x); }  // * i
__device__ __forceinline__ float2 cmulni(float2 a){ return make_float2( a.y, -a.x); }  // * -i

#define C45F 0.70710678118654752f
#define C8F  0.92387953251128674f
#define S8F  0.38268343236508977f
// * e^{-i pi/4}, * e^{-i 3pi/4}
__device__ __forceinline__ float2 mul_psi1(float2 a){ return make_float2(C45F*(a.x+a.y), C45F*(a.y-a.x)); }
__device__ __forceinline__ float2 mul_psi3(float2 a){ return make_float2(C45F*(a.y-a.x), -C45F*(a.x+a.y)); }
// * e^{+i pi/4}, * e^{+i 3pi/4}
__device__ __forceinline__ float2 mul_om1 (float2 a){ return make_float2(C45F*(a.x-a.y), C45F*(a.x+a.y)); }
__device__ __forceinline__ float2 mul_om3 (float2 a){ return make_float2(-C45F*(a.x+a.y), C45F*(a.x-a.y)); }

// Forward DIF radix-8: fuses 3 stages, first half-span M = 4s. In-place on x[8] (legs stride s).
__device__ __forceinline__ void r8_dif(float2* x, float2 w1) {
    float2 w2 = cmulf(w1, w1), w4 = cmulf(w2, w2);
    float2 y[8];
    #pragma unroll
    for (int j = 0; j < 4; ++j) { y[j] = cadd(x[j], x[j+4]); y[j+4] = csub(x[j], x[j+4]); }
    y[4] = cmulf(y[4], w1);
    y[5] = mul_psi1(cmulf(y[5], w1));
    y[6] = cmulni (cmulf(y[6], w1));
    y[7] = mul_psi3(cmulf(y[7], w1));
    float2 z[8];
    z[0]=cadd(y[0],y[2]); z[2]=cmulf (csub(y[0],y[2]), w2);
    z[1]=cadd(y[1],y[3]); z[3]=cmulni(cmulf(csub(y[1],y[3]), w2));
    z[4]=cadd(y[4],y[6]); z[6]=cmulf (csub(y[4],y[6]), w2);
    z[5]=cadd(y[5],y[7]); z[7]=cmulni(cmulf(csub(y[5],y[7]), w2));
    x[0]=cadd(z[0],z[1]); x[1]=cmulf(csub(z[0],z[1]), w4);
    x[2]=cadd(z[2],z[3]); x[3]=cmulf(csub(z[2],z[3]), w4);
    x[4]=cadd(z[4],z[5]); x[5]=cmulf(csub(z[4],z[5]), w4);
    x[6]=cadd(z[6],z[7]); x[7]=cmulf(csub(z[6],z[7]), w4);
}

// Inverse DIT radix-8: fuses 3 stages, half-spans m,2m,4m. In-place on x[8] (legs stride m).
__device__ __forceinline__ void r8_dit(float2* x, float2 v3) {
    float2 v2 = cmulf(v3, v3), v1 = cmulf(v2, v2);
    float2 y[8], t;
    t=cmulf(v1,x[1]); y[0]=cadd(x[0],t); y[1]=csub(x[0],t);
    t=cmulf(v1,x[3]); y[2]=cadd(x[2],t); y[3]=csub(x[2],t);
    t=cmulf(v1,x[5]); y[4]=cadd(x[4],t); y[5]=csub(x[4],t);
    t=cmulf(v1,x[7]); y[6]=cadd(x[6],t); y[7]=csub(x[6],t);
    float2 z[8];
    t=cmulf(v2,y[2]);        z[0]=cadd(y[0],t); z[2]=csub(y[0],t);
    t=cmuli(cmulf(v2,y[3])); z[1]=cadd(y[1],t); z[3]=csub(y[1],t);
    t=cmulf(v2,y[6]);        z[4]=cadd(y[4],t); z[6]=csub(y[4],t);
    t=cmuli(cmulf(v2,y[7])); z[5]=cadd(y[5],t); z[7]=csub(y[5],t);
    t=cmulf(v3,z[4]);          x[0]=cadd(z[0],t); x[4]=csub(z[0],t);
    t=mul_om1(cmulf(v3,z[5])); x[1]=cadd(z[1],t); x[5]=csub(z[1],t);
    t=cmuli  (cmulf(v3,z[6])); x[2]=cadd(z[2],t); x[6]=csub(z[2],t);
    t=mul_om3(cmulf(v3,z[7])); x[3]=cadd(z[3],t); x[7]=csub(z[3],t);
}

// Forward DIF radix-16 on 16 consecutive elements (half-spans 8,4,2,1). Constant twiddles.
__device__ __forceinline__ void r16_dif(float2* x) {
    float2 y[16];
    #pragma unroll
    for (int j = 0; j < 8; ++j) { y[j] = cadd(x[j], x[j+8]); y[j+8] = csub(x[j], x[j+8]); }
    y[9]  = cmulf(y[9],  make_float2( C8F, -S8F));
    y[10] = mul_psi1(y[10]);
    y[11] = cmulf(y[11], make_float2( S8F, -C8F));
    y[12] = cmulni(y[12]);
    y[13] = cmulf(y[13], make_float2(-S8F, -C8F));
    y[14] = mul_psi3(y[14]);
    y[15] = cmulf(y[15], make_float2(-C8F, -S8F));
    float2 z[16];
    #pragma unroll
    for (int g = 0; g < 16; g += 8) {
        #pragma unroll
        for (int j = 0; j < 4; ++j) { z[g+j] = cadd(y[g+j], y[g+j+4]); z[g+j+4] = csub(y[g+j], y[g+j+4]); }
        z[g+5] = mul_psi1(z[g+5]);
        z[g+6] = cmulni (z[g+6]);
        z[g+7] = mul_psi3(z[g+7]);
    }
    float2 w[16];
    #pragma unroll
    for (int g = 0; g < 16; g += 4) {
        w[g+0]=cadd(z[g+0],z[g+2]); w[g+2]=csub(z[g+0],z[g+2]);
        w[g+1]=cadd(z[g+1],z[g+3]); w[g+3]=cmulni(csub(z[g+1],z[g+3]));
    }
    #pragma unroll
    for (int g = 0; g < 16; g += 2) { x[g] = cadd(w[g], w[g+1]); x[g+1] = csub(w[g], w[g+1]); }
}

// Inverse DIT radix-16 on 16 consecutive elements (half-spans 1,2,4,8). Constant twiddles.
__device__ __forceinline__ void r16_dit(float2* x) {
    float2 y[16];
    #pragma unroll
    for (int g = 0; g < 16; g += 2) { y[g] = cadd(x[g], x[g+1]); y[g+1] = csub(x[g], x[g+1]); }
    float2 z[16];
    #pragma unroll
    for (int g = 0; g < 16; g += 4) {
        z[g+0]=cadd(y[g+0],y[g+2]); z[g+2]=csub(y[g+0],y[g+2]);
        float2 t = cmuli(y[g+3]);
        z[g+1]=cadd(y[g+1],t); z[g+3]=csub(y[g+1],t);
    }
    float2 w[16];
    #pragma unroll
    for (int g = 0; g < 16; g += 8) {
        float2 t0 = z[g+4];          w[g+0]=cadd(z[g+0],t0); w[g+4]=csub(z[g+0],t0);
        float2 t1 = mul_om1(z[g+5]); w[g+1]=cadd(z[g+1],t1); w[g+5]=csub(z[g+1],t1);
        float2 t2 = cmuli  (z[g+6]); w[g+2]=cadd(z[g+2],t2); w[g+6]=csub(z[g+2],t2);
        float2 t3 = mul_om3(z[g+7]); w[g+3]=cadd(z[g+3],t3); w[g+7]=csub(z[g+3],t3);
    }
    float2 t;
    t = w[8];                              x[0]=cadd(w[0],t); x[8] =csub(w[0],t);
    t = cmulf(w[9],  make_float2( C8F, S8F)); x[1]=cadd(w[1],t); x[9] =csub(w[1],t);
    t = mul_om1(w[10]);                    x[2]=cadd(w[2],t); x[10]=csub(w[2],t);
    t = cmulf(w[11], make_float2( S8F, C8F)); x[3]=cadd(w[3],t); x[11]=csub(w[3],t);
    t = cmuli(w[12]);                      x[4]=cadd(w[4],t); x[12]=csub(w[4],t);
    t = cmulf(w[13], make_float2(-S8F, C8F)); x[5]=cadd(w[5],t); x[13]=csub(w[5],t);
    t = mul_om3(w[14]);                    x[6]=cadd(w[6],t); x[14]=csub(w[6],t);
    t = cmulf(w[15], make_float2(-C8F, S8F)); x[7]=cadd(w[7],t); x[15]=csub(w[7],t);
}

__global__ void __launch_bounds__(BDIM, 2)
surrogate_kernel(const float* __restrict__ wave,
                 const float* __restrict__ phases,
                 const float* __restrict__ mask,
                 float* __restrict__ out)
{
    extern __shared__ float2 buf[];   // SMEMN float2 = 72 KB padded
    const int tid = threadIdx.x;
    const int blk = blockIdx.x;
    const int b  = blk >> 5;
    const int c0 = (blk & 31) * 2;

    const bool sel0 = mask[b * CC + c0]     < 0.5f;
    const bool sel1 = mask[b * CC + c0 + 1] < 0.5f;

    const float* wbase = wave + ((size_t)b * TT) * CC + c0;
    float*       obase = out  + ((size_t)b * TT) * CC + c0;

    if (!sel0 && !sel1) {
        for (int t = tid; t < TT; t += BDIM)
            *(float2*)(obase + (size_t)t * CC) = *(const float2*)(wbase + (size_t)t * CC);
        return;
    }

    const float PI_F   = 3.14159265358979f;
    const float TWO_PI = 6.28318530717959f;

    // ---- Pass A (fwd radix-8, M=4096, s=1024): gmem -> smem ----
    #pragma unroll
    for (int it = 0; it < 2; ++it) {
        int q = tid + it * BDIM;
        float2 x[8];
        #pragma unroll
        for (int j = 0; j < 8; ++j)
            x[j] = *(const float2*)(wbase + (size_t)(q + 1024 * j) * CC);
        float s, c; __sincosf(-PI_F * (float)q * (1.0f/4096.0f), &s, &c);
        r8_dif(x, make_float2(c, s));
        #pragma unroll
        for (int j = 0; j < 8; ++j) buf[PIDX(q + 1024 * j)] = x[j];
    }
    __syncthreads();

    // ---- Pass B (fwd radix-8, M=512, s=128) ----
    #pragma unroll
    for (int it = 0; it < 2; ++it) {
        int q = tid + it * BDIM;
        int t = q & 127;
        int d = ((q >> 7) << 10) + t;
        float2 x[8];
        #pragma unroll
        for (int j = 0; j < 8; ++j) x[j] = buf[PIDX(d + 128 * j)];
        float s, c; __sincosf(-PI_F * (float)t * (1.0f/512.0f), &s, &c);
        r8_dif(x, make_float2(c, s));
        #pragma unroll
        for (int j = 0; j < 8; ++j) buf[PIDX(d + 128 * j)] = x[j];
    }
    __syncthreads();

    // ---- Pass C (fwd radix-8, M=64, s=16) ----
    #pragma unroll
    for (int it = 0; it < 2; ++it) {
        int q = tid + it * BDIM;
        int t = q & 15;
        int d = ((q >> 4) << 7) + t;
        float2 x[8];
        #pragma unroll
        for (int j = 0; j < 8; ++j) x[j] = buf[PIDX(d + 16 * j)];
        float s, c; __sincosf(-PI_F * (float)t * (1.0f/64.0f), &s, &c);
        r8_dif(x, make_float2(c, s));
        #pragma unroll
        for (int j = 0; j < 8; ++j) buf[PIDX(d + 16 * j)] = x[j];
    }
    __syncthreads();

    // ---- Pass D (fwd radix-16 on 16 contiguous, half-spans 8,4,2,1) ----
    {
        float4* p4 = (float4*)(buf + 18 * tid);   // PIDX(16*tid) = 18*tid, 16B aligned
        float2 x[16];
        #pragma unroll
        for (int k = 0; k < 8; ++k) {
            float4 v = p4[k];
            x[2*k]   = make_float2(v.x, v.y);
            x[2*k+1] = make_float2(v.z, v.w);
        }
        r16_dif(x);
        #pragma unroll
        for (int k = 0; k < 8; ++k)
            p4[k] = make_float4(x[2*k].x, x[2*k].y, x[2*k+1].x, x[2*k+1].y);
    }
    __syncthreads();

    // ---- Spectral stage (bit-reversed domain) ----
    {
        const float* pbase = phases + ((size_t)b * TT) * CC + c0;
        for (int pos = tid; pos < TT; pos += BDIM) {
            int k = __brev(pos) >> (32 - LOG2T);
            if (k > TT / 2) continue;
            int kn = (TT - k) & (TT - 1);
            int pn = __brev(kn) >> (32 - LOG2T);
            float2 Zk = buf[PIDX(pos)];
            float2 Zn = buf[PIDX(pn)];
            float re0 = 0.5f * (Zk.x + Zn.x), im0 = 0.5f * (Zk.y - Zn.y);
            float re1 = 0.5f * (Zk.y + Zn.y), im1 = 0.5f * (Zn.x - Zk.x);
            float A0 = sqrtf(fmaf(re0, re0, im0 * im0));
            float A1 = sqrtf(fmaf(re1, re1, im1 * im1));
            float2 phk = *(const float2*)(pbase + (size_t)k  * CC);
            float2 phn = *(const float2*)(pbase + (size_t)kn * CC);
            float s0k, c0k, s0n, c0n, s1k, c1k, s1n, c1n;
            __sincosf(fmaf(phk.x, TWO_PI, -PI_F), &s0k, &c0k); s0k = -s0k; c0k = -c0k;
            __sincosf(fmaf(phn.x, TWO_PI, -PI_F), &s0n, &c0n); s0n = -s0n; c0n = -c0n;
            __sincosf(fmaf(phk.y, TWO_PI, -PI_F), &s1k, &c1k); s1k = -s1k; c1k = -c1k;
            __sincosf(fmaf(phn.y, TWO_PI, -PI_F), &s1n, &c1n); s1n = -s1n; c1n = -c1n;
            float S0x = 0.5f * A0 * (c0k + c0n), S0y = 0.5f * A0 * (s0k - s0n);
            float S1x = 0.5f * A1 * (c1k + c1n), S1y = 0.5f * A1 * (s1k - s1n);
            buf[PIDX(pos)] = make_float2(S0x - S1y, S0y + S1x);
            buf[PIDX(pn)]  = make_float2(S0x + S1y, S1x - S0y);
        }
    }
    __syncthreads();

    // ---- Pass E (inv radix-16 on 16 contiguous, half-spans 1,2,4,8) ----
    {
        float4* p4 = (float4*)(buf + 18 * tid);
        float2 x[16];
        #pragma unroll
        for (int k = 0; k < 8; ++k) {
            float4 v = p4[k];
            x[2*k]   = make_float2(v.x, v.y);
            x[2*k+1] = make_float2(v.z, v.w);
        }
        r16_dit(x);
        #pragma unroll
        for (int k = 0; k < 8; ++k)
            p4[k] = make_float4(x[2*k].x, x[2*k].y, x[2*k+1].x, x[2*k+1].y);
    }
    __syncthreads();

    // ---- Pass F (inv radix-8, m=16) ----
    #pragma unroll
    for (int it = 0; it < 2; ++it) {
        int q = tid + it * BDIM;
        int t = q & 15;
        int d = ((q >> 4) << 7) + t;
        float2 x[8];
        #pragma unroll
        for (int j = 0; j < 8; ++j) x[j] = buf[PIDX(d + 16 * j)];
        float s, c; __sincosf(PI_F * (float)t * (1.0f/64.0f), &s, &c);
        r8_dit(x, make_float2(c, s));
        #pragma unroll
        for (int j = 0; j < 8; ++j) buf[PIDX(d + 16 * j)] = x[j];
    }
    __syncthreads();

    // ---- Pass G (inv radix-8, m=128) ----
    #pragma unroll
    for (int it = 0; it < 2; ++it) {
        int q = tid + it * BDIM;
        int t = q & 127;
        int d = ((q >> 7) << 10) + t;
        float2 x[8];
        #pragma unroll
        for (int j = 0; j < 8; ++j) x[j] = buf[PIDX(d + 128 * j)];
        float s, c; __sincosf(PI_F * (float)t * (1.0f/512.0f), &s, &c);
        r8_dit(x, make_float2(c, s));
        #pragma unroll
        for (int j = 0; j < 8; ++j) buf[PIDX(d + 128 * j)] = x[j];
    }
    __syncthreads();

    // ---- Pass H (inv radix-8, m=1024): smem -> gmem with scale + blend ----
    const float inv = 1.0f / (float)TT;
    #pragma unroll
    for (int it = 0; it < 2; ++it) {
        int q = tid + it * BDIM;
        float2 x[8];
        #pragma unroll
        for (int j = 0; j < 8; ++j) x[j] = buf[PIDX(q + 1024 * j)];
        float s, c; __sincosf(PI_F * (float)q * (1.0f/4096.0f), &s, &c);
        r8_dit(x, make_float2(c, s));
        #pragma unroll
        for (int j = 0; j < 8; ++j) {
            int n = q + 1024 * j;
            float2 o = make_float2(x[j].x * inv, x[j].y * inv);
            if (!(sel0 && sel1)) {
                float2 wv = *(const float2*)(wbase + (size_t)n * CC);
                if (!sel0) o.x = wv.x;
                if (!sel1) o.y = wv.y;
            }
            *(float2*)(obase + (size_t)n * CC) = o;
        }
    }
}

extern "C" void kernel_launch(void* const* d_in, const int* in_sizes, int n_in,
                              void* d_out, int out_size)
{
    const float* wave   = (const float*)d_in[0];
    const float* phases = (const float*)d_in[1];
    const float* mask   = (const float*)d_in[2];
    float* out = (float*)d_out;

    cudaFuncSetAttribute(surrogate_kernel,
                         cudaFuncAttributeMaxDynamicSharedMemorySize, SMEMN * sizeof(float2));
    surrogate_kernel<<<2048, BDIM, SMEMN * sizeof(float2)>>>(wave, phases, mask, out);
}